// round 1
// baseline (speedup 1.0000x reference)
#include <cuda_runtime.h>
#include <cuda_bf16.h>

#define BB 8
#define TT 2048
#define DD 512

// Scratch: un-normalized probabilities exp(q.k/sqrt(D)) as [B*T, T], plus row sums.
__device__ float g_probs[(size_t)BB * TT * TT];
__device__ float g_sums[BB * TT];

// ---------------------------------------------------------------------------
// K1: P~[b,t,u] = exp2( (Q[b,t,:] . K[b,u,:]) * log2(e)/sqrt(D) )
// 128x128 tile, BK=16, 256 threads, 8x8 per thread. NT-gemm (both K-major).
// ---------------------------------------------------------------------------
__global__ __launch_bounds__(256) void qk_exp_kernel(const float* __restrict__ Q,
                                                     const float* __restrict__ K) {
    const int b = blockIdx.z;
    const float* Qb = Q + (size_t)b * TT * DD;
    const float* Kb = K + (size_t)b * TT * DD;
    float* Pb = g_probs + (size_t)b * TT * TT;

    const int tile_m = blockIdx.y * 128;
    const int tile_n = blockIdx.x * 128;

    __shared__ float As[16][128];  // Q^T tile: [k][m]
    __shared__ float Bs[16][128];  // K^T tile: [k][n]

    float acc[8][8];
#pragma unroll
    for (int i = 0; i < 8; i++)
#pragma unroll
        for (int j = 0; j < 8; j++) acc[i][j] = 0.f;

    const int tid = threadIdx.x;
    const int tm = (tid >> 4) << 3;   // 0..120, step 8
    const int tn = (tid & 15) << 3;   // 0..120, step 8

    for (int kt = 0; kt < DD; kt += 16) {
#pragma unroll
        for (int i = 0; i < 2; i++) {
            int f = tid + i * 256;        // float4 index in [0,512)
            int row = f >> 2;             // 4 float4 per 16-col row
            int c4 = (f & 3) << 2;
            float4 qv = *(const float4*)(Qb + (size_t)(tile_m + row) * DD + kt + c4);
            As[c4 + 0][row] = qv.x; As[c4 + 1][row] = qv.y;
            As[c4 + 2][row] = qv.z; As[c4 + 3][row] = qv.w;
            float4 kv = *(const float4*)(Kb + (size_t)(tile_n + row) * DD + kt + c4);
            Bs[c4 + 0][row] = kv.x; Bs[c4 + 1][row] = kv.y;
            Bs[c4 + 2][row] = kv.z; Bs[c4 + 3][row] = kv.w;
        }
        __syncthreads();
#pragma unroll
        for (int k = 0; k < 16; k++) {
            float a[8], bv[8];
#pragma unroll
            for (int i = 0; i < 8; i++) a[i] = As[k][tm + i];
#pragma unroll
            for (int j = 0; j < 8; j++) bv[j] = Bs[k][tn + j];
#pragma unroll
            for (int i = 0; i < 8; i++)
#pragma unroll
                for (int j = 0; j < 8; j++)
                    acc[i][j] = fmaf(a[i], bv[j], acc[i][j]);
        }
        __syncthreads();
    }

    // exp2(score * log2(e)/sqrt(512)); logits ~ N(0,1) so no max-subtraction needed.
    const float scl = 1.4426950408889634f * 0.04419417382415922f;
#pragma unroll
    for (int i = 0; i < 8; i++) {
        size_t rbase = (size_t)(tile_m + tm + i) * TT + tile_n + tn;
#pragma unroll
        for (int j = 0; j < 8; j += 4) {
            float4 o;
            o.x = exp2f(acc[i][j + 0] * scl);
            o.y = exp2f(acc[i][j + 1] * scl);
            o.z = exp2f(acc[i][j + 2] * scl);
            o.w = exp2f(acc[i][j + 3] * scl);
            *(float4*)(Pb + rbase + j) = o;
        }
    }
}

// ---------------------------------------------------------------------------
// K2: g_sums[row] = sum_u g_probs[row, u], one 256-thread block per row.
// ---------------------------------------------------------------------------
__global__ __launch_bounds__(256) void rowsum_kernel() {
    const size_t row = blockIdx.x;
    const float* p = g_probs + row * (size_t)TT;
    float s = 0.f;
    for (int i = threadIdx.x * 4; i < TT; i += 256 * 4) {
        float4 v = *(const float4*)(p + i);
        s += v.x + v.y + v.z + v.w;
    }
#pragma unroll
    for (int o = 16; o; o >>= 1) s += __shfl_xor_sync(0xFFFFFFFFu, s, o);
    __shared__ float ws[8];
    if ((threadIdx.x & 31) == 0) ws[threadIdx.x >> 5] = s;
    __syncthreads();
    if (threadIdx.x < 8) {
        s = ws[threadIdx.x];
#pragma unroll
        for (int o = 4; o; o >>= 1) s += __shfl_xor_sync(0xFFu, s, o);
        if (threadIdx.x == 0) g_sums[row] = s;
    }
}

// ---------------------------------------------------------------------------
// K3: Out[b,t,d] = (sum_u P~[b,t,u] * S[b,u,d]) * V[b,t,d] / g_sums[b,t]
// NN-gemm: A = P~ [T,T] (K-major), B = S [T,D].
// ---------------------------------------------------------------------------
__global__ __launch_bounds__(256) void pv_kernel(const float* __restrict__ S,
                                                 const float* __restrict__ V,
                                                 float* __restrict__ Out) {
    const int b = blockIdx.z;
    const float* Pb = g_probs + (size_t)b * TT * TT;
    const float* Sb = S + (size_t)b * TT * DD;
    const float* Vb = V + (size_t)b * TT * DD;
    float* Ob = Out + (size_t)b * TT * DD;

    const int tile_m = blockIdx.y * 128;  // t
    const int tile_n = blockIdx.x * 128;  // d

    __shared__ float As[16][128];  // P^T tile: [k][m]
    __shared__ float Bs[16][128];  // S tile:   [k][n]

    float acc[8][8];
#pragma unroll
    for (int i = 0; i < 8; i++)
#pragma unroll
        for (int j = 0; j < 8; j++) acc[i][j] = 0.f;

    const int tid = threadIdx.x;
    const int tm = (tid >> 4) << 3;
    const int tn = (tid & 15) << 3;

    for (int kt = 0; kt < TT; kt += 16) {
#pragma unroll
        for (int i = 0; i < 2; i++) {
            int f = tid + i * 256;  // float4 index in [0,512)
            // P tile: 128 rows(t) x 16 cols(u)
            int row = f >> 2;
            int c4 = (f & 3) << 2;
            float4 pv = *(const float4*)(Pb + (size_t)(tile_m + row) * TT + kt + c4);
            As[c4 + 0][row] = pv.x; As[c4 + 1][row] = pv.y;
            As[c4 + 2][row] = pv.z; As[c4 + 3][row] = pv.w;
            // S tile: 16 rows(u) x 128 cols(d) — direct layout
            int srow = f >> 5;            // 32 float4 per 128-col row
            int sc = (f & 31) << 2;
            float4 sv = *(const float4*)(Sb + (size_t)(kt + srow) * DD + tile_n + sc);
            *(float4*)&Bs[srow][sc] = sv;
        }
        __syncthreads();
#pragma unroll
        for (int k = 0; k < 16; k++) {
            float a[8], bv[8];
#pragma unroll
            for (int i = 0; i < 8; i++) a[i] = As[k][tm + i];
#pragma unroll
            for (int j = 0; j < 8; j++) bv[j] = Bs[k][tn + j];
#pragma unroll
            for (int i = 0; i < 8; i++)
#pragma unroll
                for (int j = 0; j < 8; j++)
                    acc[i][j] = fmaf(a[i], bv[j], acc[i][j]);
        }
        __syncthreads();
    }

#pragma unroll
    for (int i = 0; i < 8; i++) {
        const int r = tile_m + tm + i;
        const float inv = 1.0f / g_sums[b * TT + r];
        const size_t base = (size_t)r * DD + tile_n + tn;
#pragma unroll
        for (int j = 0; j < 8; j += 4) {
            float4 vv = *(const float4*)(Vb + base + j);
            float4 o;
            o.x = acc[i][j + 0] * inv * vv.x;
            o.y = acc[i][j + 1] * inv * vv.y;
            o.z = acc[i][j + 2] * inv * vv.z;
            o.w = acc[i][j + 3] * inv * vv.w;
            *(float4*)(Ob + base + j) = o;
        }
    }
}

extern "C" void kernel_launch(void* const* d_in, const int* in_sizes, int n_in,
                              void* d_out, int out_size) {
    const float* q = (const float*)d_in[0];
    const float* k = (const float*)d_in[1];
    const float* v = (const float*)d_in[2];
    const float* s = (const float*)d_in[3];
    float* out = (float*)d_out;

    dim3 g1(TT / 128, TT / 128, BB);   // 16 x 16 x 8
    qk_exp_kernel<<<g1, 256>>>(q, k);

    rowsum_kernel<<<BB * TT, 256>>>();

    dim3 g2(DD / 128, TT / 128, BB);   // 4 x 16 x 8
    pv_kernel<<<g2, 256>>>(s, v, out);
}

// round 6
// speedup vs baseline: 2.0823x; 2.0823x over previous
#include <cuda_runtime.h>
#include <cuda_bf16.h>
#include <cstdint>

#define BB 8
#define TT 2048
#define DD 512
#define KC 32                       // k-chunk (bf16 elements)
#define PITCH 40                    // smem row pitch in bf16 (32 data + 8 pad) = 80B
#define ARR (128 * PITCH * 2)       // one array: 10240 B
#define SB (4 * ARR)                // stage: Ah, Al, Bh, Bl = 40960 B
#define DYN_SMEM (3 * SB)           // 122880 B

typedef __nv_bfloat16 bf16;

// ---------------- global scratch ----------------
__device__ __align__(1024) bf16 g_Qhi[(size_t)BB * TT * DD];
__device__ __align__(1024) bf16 g_Qlo[(size_t)BB * TT * DD];
__device__ __align__(1024) bf16 g_Khi[(size_t)BB * TT * DD];
__device__ __align__(1024) bf16 g_Klo[(size_t)BB * TT * DD];
__device__ __align__(1024) bf16 g_SThi[(size_t)BB * DD * TT];  // [b][d][t]
__device__ __align__(1024) bf16 g_STlo[(size_t)BB * DD * TT];
__device__ __align__(1024) bf16 g_Phi[(size_t)BB * TT * TT];
__device__ __align__(1024) bf16 g_Plo[(size_t)BB * TT * TT];
__device__ float g_sums[BB * TT];

// ---------------- PTX helpers (sm_80-era, legal on compute_103) ------------
__device__ __forceinline__ uint32_t smem_u32(const void* p) {
    uint32_t a;
    asm("{ .reg .u64 t; cvta.to.shared.u64 t, %1; cvt.u32.u64 %0, t; }" : "=r"(a) : "l"(p));
    return a;
}
__device__ __forceinline__ void cp16(uint32_t dst, const void* src) {
    asm volatile("cp.async.cg.shared.global [%0], [%1], 16;" :: "r"(dst), "l"(src) : "memory");
}
__device__ __forceinline__ void cp_commit() {
    asm volatile("cp.async.commit_group;" ::: "memory");
}
__device__ __forceinline__ void cp_wait1() {
    asm volatile("cp.async.wait_group 1;" ::: "memory");
}
__device__ __forceinline__ uint32_t lds32(uint32_t addr) {
    uint32_t v;
    asm volatile("ld.shared.b32 %0, [%1];" : "=r"(v) : "r"(addr));
    return v;
}
__device__ __forceinline__ void mma16816(float* c, const uint32_t* a, const uint32_t* b) {
    asm volatile(
        "mma.sync.aligned.m16n8k16.row.col.f32.bf16.bf16.f32 "
        "{%0,%1,%2,%3}, {%4,%5,%6,%7}, {%8,%9}, {%0,%1,%2,%3};"
        : "+f"(c[0]), "+f"(c[1]), "+f"(c[2]), "+f"(c[3])
        : "r"(a[0]), "r"(a[1]), "r"(a[2]), "r"(a[3]), "r"(b[0]), "r"(b[1]));
}
__device__ __forceinline__ float ex2(float x) {
    float r;
    asm("ex2.approx.ftz.f32 %0, %1;" : "=f"(r) : "f"(x));
    return r;
}
__device__ __forceinline__ unsigned pk(bf16 a, bf16 b) {
    __nv_bfloat162 t = __halves2bfloat162(a, b);
    return *reinterpret_cast<unsigned*>(&t);
}

// ---------------- stage loader: rows 0..127, 4x16B chunks per row ----------
// Layout: array base + row*80 + chunk*16  (16B pad at end of each 80B row).
__device__ __forceinline__ void ldstage(uint32_t st,
                                        const bf16* ah, const bf16* al, size_t lda,
                                        const bf16* bh, const bf16* bl, size_t ldb,
                                        int k0, int tid) {
#pragma unroll
    for (int it = 0; it < 2; it++) {
        int f = tid + it * 256;            // 0..511
        int r = f >> 2, c = f & 3;
        uint32_t d = st + (uint32_t)(r * (PITCH * 2) + c * 16);
        size_t oa = (size_t)r * lda + k0 + c * 8;
        size_t ob = (size_t)r * ldb + k0 + c * 8;
        cp16(d,            ah + oa);
        cp16(d + ARR,      al + oa);
        cp16(d + 2 * ARR,  bh + ob);
        cp16(d + 3 * ARR,  bl + ob);
    }
}

// ---------------- HMMA mainloop: D(128x128) = A @ B^T, 3-term split --------
// Fragment loads follow the PTX ISA m16n8k16 layouts literally:
//   a0 = A[g][2q], a1 = A[g+8][2q], a2 = A[g][2q+8], a3 = A[g+8][2q+8]
//   b0 = Bt[g][2q], b1 = Bt[g][2q+8]        (g = lane/4, q = lane%4)
__device__ __forceinline__ void gemm_main(const bf16* ah, const bf16* al, size_t lda,
                                          const bf16* bh, const bf16* bl, size_t ldb,
                                          int NC, uint32_t smem, float acc[4][4][4]) {
    const int tid = threadIdx.x;
    const int lane = tid & 31;
    const int wid = tid >> 5;
    const int wm = wid >> 2;      // 0..1 -> 64-row half
    const int wn = wid & 3;       // 0..3 -> 32-col quarter

#pragma unroll
    for (int mt = 0; mt < 4; mt++)
#pragma unroll
        for (int nt = 0; nt < 4; nt++)
#pragma unroll
            for (int u = 0; u < 4; u++) acc[mt][nt][u] = 0.f;

    const int g = lane >> 2;          // 0..7
    const int q = lane & 3;           // 0..3

    ldstage(smem, ah, al, lda, bh, bl, ldb, 0, tid);
    cp_commit();
    ldstage(smem + SB, ah, al, lda, bh, bl, ldb, KC, tid);
    cp_commit();

    for (int i = 0; i < NC; i++) {
        cp_wait1();
        __syncthreads();
        const int j = i + 2;
        if (j < NC)
            ldstage(smem + (j % 3) * SB, ah, al, lda, bh, bl, ldb, j * KC, tid);
        cp_commit();

        const uint32_t sa = smem + (i % 3) * SB;
#pragma unroll
        for (int ks = 0; ks < 2; ks++) {
            // byte offset of this thread's k element within the 64B data row
            const uint32_t kb = (uint32_t)(ks * 32 + q * 4);
            uint32_t afh[4][4], afl[4][4];
#pragma unroll
            for (int mt = 0; mt < 4; mt++) {
                const uint32_t r0 = (uint32_t)((wm * 64 + mt * 16 + g) * (PITCH * 2));
                uint32_t a00 = sa + r0 + kb;                   // A[g][2q]
                afh[mt][0] = lds32(a00);
                afh[mt][1] = lds32(a00 + 8 * (PITCH * 2));     // A[g+8][2q]
                afh[mt][2] = lds32(a00 + 16);                  // A[g][2q+8]
                afh[mt][3] = lds32(a00 + 8 * (PITCH * 2) + 16);
                uint32_t a01 = a00 + ARR;
                afl[mt][0] = lds32(a01);
                afl[mt][1] = lds32(a01 + 8 * (PITCH * 2));
                afl[mt][2] = lds32(a01 + 16);
                afl[mt][3] = lds32(a01 + 8 * (PITCH * 2) + 16);
            }
#pragma unroll
            for (int nt = 0; nt < 4; nt++) {
                const uint32_t rb = (uint32_t)((wn * 32 + nt * 8 + g) * (PITCH * 2));
                uint32_t b00 = sa + 2 * ARR + rb + kb;         // Bt[g][2q]
                uint32_t bfh[2], bfl[2];
                bfh[0] = lds32(b00);
                bfh[1] = lds32(b00 + 16);                      // Bt[g][2q+8]
                bfl[0] = lds32(b00 + ARR);
                bfl[1] = lds32(b00 + ARR + 16);
#pragma unroll
                for (int mt = 0; mt < 4; mt++) {
                    mma16816(acc[mt][nt], afh[mt], bfh);
                    mma16816(acc[mt][nt], afh[mt], bfl);
                    mma16816(acc[mt][nt], afl[mt], bfh);
                }
            }
        }
    }
}

// ---------------- K1: P~ = exp(QK^T * scale) -> bf16 hi/lo -----------------
__global__ __launch_bounds__(256) void qk_kernel() {
    extern __shared__ char dyn_smem[];
    const uint32_t smem = smem_u32(dyn_smem);
    const int tid = threadIdx.x;
    const int lane = tid & 31;
    const int wid = tid >> 5;
    const int wm = wid >> 2, wn = wid & 3;
    const int b = blockIdx.z;
    const int tile_m = blockIdx.y * 128;
    const int tile_n = blockIdx.x * 128;

    float acc[4][4][4];
    gemm_main(g_Qhi + ((size_t)b * TT + tile_m) * DD,
              g_Qlo + ((size_t)b * TT + tile_m) * DD, DD,
              g_Khi + ((size_t)b * TT + tile_n) * DD,
              g_Klo + ((size_t)b * TT + tile_n) * DD, DD,
              DD / KC, smem, acc);

    const float SCL = 1.4426950408889634f * 0.04419417382415922f;
    bf16* Ph = g_Phi + (size_t)b * TT * TT;
    bf16* Pl = g_Plo + (size_t)b * TT * TT;
#pragma unroll
    for (int mt = 0; mt < 4; mt++) {
        const int r0 = tile_m + wm * 64 + mt * 16 + (lane >> 2);
        const int r1 = r0 + 8;
#pragma unroll
        for (int nt = 0; nt < 4; nt++) {
            const int c0 = tile_n + wn * 32 + nt * 8 + (lane & 3) * 2;
            float p0 = ex2(acc[mt][nt][0] * SCL);
            float p1 = ex2(acc[mt][nt][1] * SCL);
            float p2 = ex2(acc[mt][nt][2] * SCL);
            float p3 = ex2(acc[mt][nt][3] * SCL);
            bf16 h0 = __float2bfloat16(p0), h1 = __float2bfloat16(p1);
            bf16 h2 = __float2bfloat16(p2), h3 = __float2bfloat16(p3);
            bf16 l0 = __float2bfloat16(p0 - __bfloat162float(h0));
            bf16 l1 = __float2bfloat16(p1 - __bfloat162float(h1));
            bf16 l2 = __float2bfloat16(p2 - __bfloat162float(h2));
            bf16 l3 = __float2bfloat16(p3 - __bfloat162float(h3));
            *reinterpret_cast<uint32_t*>(Ph + (size_t)r0 * TT + c0) = pk(h0, h1);
            *reinterpret_cast<uint32_t*>(Ph + (size_t)r1 * TT + c0) = pk(h2, h3);
            *reinterpret_cast<uint32_t*>(Pl + (size_t)r0 * TT + c0) = pk(l0, l1);
            *reinterpret_cast<uint32_t*>(Pl + (size_t)r1 * TT + c0) = pk(l2, l3);
        }
    }
}

// ---------------- rowsum over Phi+Plo --------------------------------------
__global__ __launch_bounds__(256) void rowsum_kernel() {
    const size_t row = blockIdx.x;
    const uint4* ph = reinterpret_cast<const uint4*>(g_Phi + row * TT);
    const uint4* pl = reinterpret_cast<const uint4*>(g_Plo + row * TT);
    uint4 a = ph[threadIdx.x];
    uint4 c = pl[threadIdx.x];
    const __nv_bfloat162* ha = reinterpret_cast<const __nv_bfloat162*>(&a);
    const __nv_bfloat162* hc = reinterpret_cast<const __nv_bfloat162*>(&c);
    float s = 0.f;
#pragma unroll
    for (int u = 0; u < 4; u++) {
        float2 fa = __bfloat1622float2(ha[u]);
        float2 fc = __bfloat1622float2(hc[u]);
        s += (fa.x + fc.x) + (fa.y + fc.y);
    }
#pragma unroll
    for (int o = 16; o; o >>= 1) s += __shfl_xor_sync(0xFFFFFFFFu, s, o);
    __shared__ float ws[8];
    if ((threadIdx.x & 31) == 0) ws[threadIdx.x >> 5] = s;
    __syncthreads();
    if (threadIdx.x < 8) {
        s = ws[threadIdx.x];
#pragma unroll
        for (int o = 4; o; o >>= 1) s += __shfl_xor_sync(0xFFu, s, o);
        if (threadIdx.x == 0) g_sums[row] = s;
    }
}

// ---------------- K3: out = (P~ @ S) * V / rowsum --------------------------
__global__ __launch_bounds__(256) void pv_kernel(const float* __restrict__ V,
                                                 float* __restrict__ Out) {
    extern __shared__ char dyn_smem[];
    const uint32_t smem = smem_u32(dyn_smem);
    const int tid = threadIdx.x;
    const int lane = tid & 31;
    const int wid = tid >> 5;
    const int wm = wid >> 2, wn = wid & 3;
    const int b = blockIdx.z;
    const int tile_m = blockIdx.y * 128;   // t
    const int tile_n = blockIdx.x * 128;   // d

    float acc[4][4][4];
    gemm_main(g_Phi + ((size_t)b * TT + tile_m) * TT,
              g_Plo + ((size_t)b * TT + tile_m) * TT, TT,
              g_SThi + ((size_t)b * DD + tile_n) * TT,
              g_STlo + ((size_t)b * DD + tile_n) * TT, TT,
              TT / KC, smem, acc);

    const float* Vb = V + (size_t)b * TT * DD;
    float* Ob = Out + (size_t)b * TT * DD;
    const float* sums = g_sums + b * TT;
#pragma unroll
    for (int mt = 0; mt < 4; mt++) {
        const int r0 = tile_m + wm * 64 + mt * 16 + (lane >> 2);
        const int r1 = r0 + 8;
        const float inv0 = 1.0f / sums[r0];
        const float inv1 = 1.0f / sums[r1];
#pragma unroll
        for (int nt = 0; nt < 4; nt++) {
            const int c0 = tile_n + wn * 32 + nt * 8 + (lane & 3) * 2;
            float2 v0 = *reinterpret_cast<const float2*>(Vb + (size_t)r0 * DD + c0);
            float2 v1 = *reinterpret_cast<const float2*>(Vb + (size_t)r1 * DD + c0);
            float2 o0, o1;
            o0.x = acc[mt][nt][0] * inv0 * v0.x;
            o0.y = acc[mt][nt][1] * inv0 * v0.y;
            o1.x = acc[mt][nt][2] * inv1 * v1.x;
            o1.y = acc[mt][nt][3] * inv1 * v1.y;
            *reinterpret_cast<float2*>(Ob + (size_t)r0 * DD + c0) = o0;
            *reinterpret_cast<float2*>(Ob + (size_t)r1 * DD + c0) = o1;
        }
    }
}

// ---------------- fp32 -> bf16 hi/lo conversions ---------------------------
// NOTE: destinations resolved IN DEVICE CODE via selector. Passing __device__
// global symbols as host-side kernel args silently yields the HOST shadow
// address (ATS writes land in host memory on GB300) — that was the R4/R5 bug.
__global__ __launch_bounds__(256) void conv_hl_kernel(const float* __restrict__ src,
                                                      int which) {
    bf16* hi = (which == 0) ? g_Qhi : g_Khi;
    bf16* lo = (which == 0) ? g_Qlo : g_Klo;
    size_t i4 = (size_t)blockIdx.x * 256 + threadIdx.x;
    float4 v = reinterpret_cast<const float4*>(src)[i4];
    bf16 h0 = __float2bfloat16(v.x), h1 = __float2bfloat16(v.y);
    bf16 h2 = __float2bfloat16(v.z), h3 = __float2bfloat16(v.w);
    bf16 l0 = __float2bfloat16(v.x - __bfloat162float(h0));
    bf16 l1 = __float2bfloat16(v.y - __bfloat162float(h1));
    bf16 l2 = __float2bfloat16(v.z - __bfloat162float(h2));
    bf16 l3 = __float2bfloat16(v.w - __bfloat162float(h3));
    reinterpret_cast<uint2*>(hi)[i4] = make_uint2(pk(h0, h1), pk(h2, h3));
    reinterpret_cast<uint2*>(lo)[i4] = make_uint2(pk(l0, l1), pk(l2, l3));
}

// transpose S[b][t][d] -> St[b][d][t] with hi/lo split
__global__ void conv_sT_kernel(const float* __restrict__ S) {
    __shared__ float t[32][33];
    const int b = blockIdx.z;
    const int t0 = blockIdx.x * 32, d0 = blockIdx.y * 32;
    const int x = threadIdx.x, y = threadIdx.y;
    const float* Sb = S + (size_t)b * TT * DD;
#pragma unroll
    for (int i = 0; i < 32; i += 8)
        t[y + i][x] = Sb[(size_t)(t0 + y + i) * DD + d0 + x];
    __syncthreads();
    bf16* Hb = g_SThi + (size_t)b * DD * TT;
    bf16* Lb = g_STlo + (size_t)b * DD * TT;
#pragma unroll
    for (int i = 0; i < 32; i += 8) {
        const int d = d0 + y + i;
        float v = t[x][y + i];
        bf16 h = __float2bfloat16(v);
        Hb[(size_t)d * TT + t0 + x] = h;
        Lb[(size_t)d * TT + t0 + x] = __float2bfloat16(v - __bfloat162float(h));
    }
}

// ---------------- host -----------------------------------------------------
extern "C" void kernel_launch(void* const* d_in, const int* in_sizes, int n_in,
                              void* d_out, int out_size) {
    const float* q = (const float*)d_in[0];
    const float* k = (const float*)d_in[1];
    const float* v = (const float*)d_in[2];
    const float* s = (const float*)d_in[3];
    float* out = (float*)d_out;

    cudaFuncSetAttribute(qk_kernel, cudaFuncAttributeMaxDynamicSharedMemorySize, DYN_SMEM);
    cudaFuncSetAttribute(pv_kernel, cudaFuncAttributeMaxDynamicSharedMemorySize, DYN_SMEM);

    const int n4 = BB * TT * DD / 4;
    conv_hl_kernel<<<n4 / 256, 256>>>(q, 0);
    conv_hl_kernel<<<n4 / 256, 256>>>(k, 1);
    conv_sT_kernel<<<dim3(TT / 32, DD / 32, BB), dim3(32, 8)>>>(s);

    qk_kernel<<<dim3(TT / 128, TT / 128, BB), 256, DYN_SMEM>>>();
    rowsum_kernel<<<BB * TT, 256>>>();
    pv_kernel<<<dim3(DD / 128, TT / 128, BB), 256, DYN_SMEM>>>(v, out);
}

// round 10
// speedup vs baseline: 2.4798x; 1.1909x over previous
#include <cuda_runtime.h>
#include <cuda_bf16.h>
#include <cstdint>

#define BB 8
#define TT 2048
#define DD 512
#define KC 32                       // k-chunk (bf16 elements)
#define PITCH 40                    // smem row pitch in bf16 (32 data + 8 pad) = 80B
#define ARR (128 * PITCH * 2)       // one array: 10240 B
#define SB (4 * ARR)                // stage: Ah, Al, Bh, Bl = 40960 B
#define DYN_SMEM (2 * SB)           // 81920 B -> 2 CTAs/SM

typedef __nv_bfloat16 bf16;

// ---------------- global scratch ----------------
__device__ __align__(1024) bf16 g_Qhi[(size_t)BB * TT * DD];
__device__ __align__(1024) bf16 g_Qlo[(size_t)BB * TT * DD];
__device__ __align__(1024) bf16 g_Khi[(size_t)BB * TT * DD];
__device__ __align__(1024) bf16 g_Klo[(size_t)BB * TT * DD];
__device__ __align__(1024) bf16 g_SThi[(size_t)BB * DD * TT];  // [b][d][t]
__device__ __align__(1024) bf16 g_STlo[(size_t)BB * DD * TT];
__device__ __align__(1024) bf16 g_Phi[(size_t)BB * TT * TT];
__device__ __align__(1024) bf16 g_Plo[(size_t)BB * TT * TT];
__device__ float g_part[(size_t)BB * TT * 64];   // per-(row, tile_x*4+wn) partial sums
__device__ float g_sums[BB * TT];

// ---------------- PTX helpers (sm_80-era, legal on compute_103) ------------
__device__ __forceinline__ uint32_t smem_u32(const void* p) {
    uint32_t a;
    asm("{ .reg .u64 t; cvta.to.shared.u64 t, %1; cvt.u32.u64 %0, t; }" : "=r"(a) : "l"(p));
    return a;
}
__device__ __forceinline__ void cp16(uint32_t dst, const void* src) {
    asm volatile("cp.async.cg.shared.global [%0], [%1], 16;" :: "r"(dst), "l"(src) : "memory");
}
__device__ __forceinline__ void cp_commit() {
    asm volatile("cp.async.commit_group;" ::: "memory");
}
__device__ __forceinline__ void cp_wait1() {
    asm volatile("cp.async.wait_group 1;" ::: "memory");
}
__device__ __forceinline__ void cp_wait0() {
    asm volatile("cp.async.wait_group 0;" ::: "memory");
}
__device__ __forceinline__ void ldm_x4(uint32_t* d, uint32_t addr) {
    asm volatile("ldmatrix.sync.aligned.m8n8.x4.shared.b16 {%0,%1,%2,%3}, [%4];"
                 : "=r"(d[0]), "=r"(d[1]), "=r"(d[2]), "=r"(d[3]) : "r"(addr));
}
__device__ __forceinline__ void ldm_x2(uint32_t* d, uint32_t addr) {
    asm volatile("ldmatrix.sync.aligned.m8n8.x2.shared.b16 {%0,%1}, [%2];"
                 : "=r"(d[0]), "=r"(d[1]) : "r"(addr));
}
__device__ __forceinline__ void mma16816(float* c, const uint32_t* a, const uint32_t* b) {
    asm volatile(
        "mma.sync.aligned.m16n8k16.row.col.f32.bf16.bf16.f32 "
        "{%0,%1,%2,%3}, {%4,%5,%6,%7}, {%8,%9}, {%0,%1,%2,%3};"
        : "+f"(c[0]), "+f"(c[1]), "+f"(c[2]), "+f"(c[3])
        : "r"(a[0]), "r"(a[1]), "r"(a[2]), "r"(a[3]), "r"(b[0]), "r"(b[1]));
}
__device__ __forceinline__ float ex2(float x) {
    float r;
    asm("ex2.approx.ftz.f32 %0, %1;" : "=f"(r) : "f"(x));
    return r;
}
__device__ __forceinline__ unsigned pk(bf16 a, bf16 b) {
    __nv_bfloat162 t = __halves2bfloat162(a, b);
    return *reinterpret_cast<unsigned*>(&t);
}

// ---------------- stage loader: rows 0..127, 4x16B chunks per row ----------
__device__ __forceinline__ void ldstage(uint32_t st,
                                        const bf16* ah, const bf16* al, size_t lda,
                                        const bf16* bh, const bf16* bl, size_t ldb,
                                        int k0, int tid) {
#pragma unroll
    for (int it = 0; it < 2; it++) {
        int f = tid + it * 256;            // 0..511
        int r = f >> 2, c = f & 3;
        uint32_t d = st + (uint32_t)(r * (PITCH * 2) + c * 16);
        size_t oa = (size_t)r * lda + k0 + c * 8;
        size_t ob = (size_t)r * ldb + k0 + c * 8;
        cp16(d,            ah + oa);
        cp16(d + ARR,      al + oa);
        cp16(d + 2 * ARR,  bh + ob);
        cp16(d + 3 * ARR,  bl + ob);
    }
}

// ---------------- HMMA mainloop: D(128x128) = A @ B^T, 3-term split --------
// Fragments via ldmatrix on the padded (conflict-free) layout. Register
// distribution of ldmatrix.m8n8 matches the PTX mma fragment formulas that the
// round-6 scalar-LDS version validated.
__device__ __forceinline__ void gemm_main(const bf16* ah, const bf16* al, size_t lda,
                                          const bf16* bh, const bf16* bl, size_t ldb,
                                          int NC, uint32_t smem, float acc[4][4][4]) {
    const int tid = threadIdx.x;
    const int lane = tid & 31;
    const int wid = tid >> 5;
    const int wm = wid >> 2;      // 0..1 -> 64-row half
    const int wn = wid & 3;       // 0..3 -> 32-col quarter

#pragma unroll
    for (int mt = 0; mt < 4; mt++)
#pragma unroll
        for (int nt = 0; nt < 4; nt++)
#pragma unroll
            for (int u = 0; u < 4; u++) acc[mt][nt][u] = 0.f;

    // ldmatrix lane-address roles
    const int arow = lane & 15;          // A row within 16-row block
    const int akc  = lane >> 4;          // 0/1: k half (8 cols = 16B)
    const int brow = lane & 7;           // B row within 8-row block
    const int bkc  = (lane >> 3) & 1;    // 0/1: k half (lanes 0-15 used)

    ldstage(smem, ah, al, lda, bh, bl, ldb, 0, tid);
    cp_commit();

    for (int i = 0; i < NC; i++) {
        const int j = i + 1;
        if (j < NC) {
            ldstage(smem + (j & 1) * SB, ah, al, lda, bh, bl, ldb, j * KC, tid);
            cp_commit();
            cp_wait1();
        } else {
            cp_wait0();
        }
        __syncthreads();

        const uint32_t sa = smem + (i & 1) * SB;
#pragma unroll
        for (int ks = 0; ks < 2; ks++) {
            uint32_t afh[4][4], afl[4][4];
#pragma unroll
            for (int mt = 0; mt < 4; mt++) {
                uint32_t aaddr = sa
                    + (uint32_t)((wm * 64 + mt * 16 + arow) * (PITCH * 2))
                    + (uint32_t)((ks * 2 + akc) * 16);
                ldm_x4(afh[mt], aaddr);
                ldm_x4(afl[mt], aaddr + ARR);
            }
#pragma unroll
            for (int nt = 0; nt < 4; nt++) {
                uint32_t baddr = sa + 2 * ARR
                    + (uint32_t)((wn * 32 + nt * 8 + brow) * (PITCH * 2))
                    + (uint32_t)((ks * 2 + bkc) * 16);
                uint32_t bfh[2], bfl[2];
                ldm_x2(bfh, baddr);
                ldm_x2(bfl, baddr + ARR);
#pragma unroll
                for (int mt = 0; mt < 4; mt++) {
                    mma16816(acc[mt][nt], afh[mt], bfh);
                    mma16816(acc[mt][nt], afh[mt], bfl);
                    mma16816(acc[mt][nt], afl[mt], bfh);
                }
            }
        }
        __syncthreads();
    }
}

// ---------------- K1: P~ = exp(QK^T * scale) -> bf16 hi/lo + partial sums --
__global__ __launch_bounds__(256, 2) void qk_kernel() {
    extern __shared__ char dyn_smem[];
    const uint32_t smem = smem_u32(dyn_smem);
    const int tid = threadIdx.x;
    const int lane = tid & 31;
    const int wid = tid >> 5;
    const int wm = wid >> 2, wn = wid & 3;
    const int q = lane & 3;
    const int b = blockIdx.z;
    const int tile_m = blockIdx.y * 128;
    const int tile_n = blockIdx.x * 128;

    float acc[4][4][4];
    gemm_main(g_Qhi + ((size_t)b * TT + tile_m) * DD,
              g_Qlo + ((size_t)b * TT + tile_m) * DD, DD,
              g_Khi + ((size_t)b * TT + tile_n) * DD,
              g_Klo + ((size_t)b * TT + tile_n) * DD, DD,
              DD / KC, smem, acc);

    const float SCL = 1.4426950408889634f * 0.04419417382415922f;
    bf16* Ph = g_Phi + (size_t)b * TT * TT;
    bf16* Pl = g_Plo + (size_t)b * TT * TT;
#pragma unroll
    for (int mt = 0; mt < 4; mt++) {
        const int r0 = tile_m + wm * 64 + mt * 16 + (lane >> 2);
        const int r1 = r0 + 8;
        float rs0 = 0.f, rs1 = 0.f;
#pragma unroll
        for (int nt = 0; nt < 4; nt++) {
            const int c0 = tile_n + wn * 32 + nt * 8 + q * 2;
            float p0 = ex2(acc[mt][nt][0] * SCL);
            float p1 = ex2(acc[mt][nt][1] * SCL);
            float p2 = ex2(acc[mt][nt][2] * SCL);
            float p3 = ex2(acc[mt][nt][3] * SCL);
            rs0 += p0 + p1;
            rs1 += p2 + p3;
            bf16 h0 = __float2bfloat16(p0), h1 = __float2bfloat16(p1);
            bf16 h2 = __float2bfloat16(p2), h3 = __float2bfloat16(p3);
            bf16 l0 = __float2bfloat16(p0 - __bfloat162float(h0));
            bf16 l1 = __float2bfloat16(p1 - __bfloat162float(h1));
            bf16 l2 = __float2bfloat16(p2 - __bfloat162float(h2));
            bf16 l3 = __float2bfloat16(p3 - __bfloat162float(h3));
            *reinterpret_cast<uint32_t*>(Ph + (size_t)r0 * TT + c0) = pk(h0, h1);
            *reinterpret_cast<uint32_t*>(Ph + (size_t)r1 * TT + c0) = pk(h2, h3);
            *reinterpret_cast<uint32_t*>(Pl + (size_t)r0 * TT + c0) = pk(l0, l1);
            *reinterpret_cast<uint32_t*>(Pl + (size_t)r1 * TT + c0) = pk(l2, l3);
        }
        // reduce across the quad (lanes sharing a row) -> per-warp row partials
        rs0 += __shfl_xor_sync(0xFFFFFFFFu, rs0, 1);
        rs0 += __shfl_xor_sync(0xFFFFFFFFu, rs0, 2);
        rs1 += __shfl_xor_sync(0xFFFFFFFFu, rs1, 1);
        rs1 += __shfl_xor_sync(0xFFFFFFFFu, rs1, 2);
        if (q == 0) {
            const int col = blockIdx.x * 4 + wn;
            g_part[((size_t)b * TT + r0) * 64 + col] = rs0;
            g_part[((size_t)b * TT + r1) * 64 + col] = rs1;
        }
    }
}

// ---------------- reduce 64 partials per row -> g_sums ---------------------
__global__ __launch_bounds__(256) void sumpart_kernel() {
    const int row = blockIdx.x * 8 + (threadIdx.x >> 5);
    const int lane = threadIdx.x & 31;
    const float* p = g_part + (size_t)row * 64;
    float s = p[lane] + p[lane + 32];
#pragma unroll
    for (int o = 16; o; o >>= 1) s += __shfl_xor_sync(0xFFFFFFFFu, s, o);
    if (lane == 0) g_sums[row] = s;
}

// ---------------- K3: out = (P~ @ S) * V / rowsum --------------------------
__global__ __launch_bounds__(256, 2) void pv_kernel(const float* __restrict__ V,
                                                    float* __restrict__ Out) {
    extern __shared__ char dyn_smem[];
    const uint32_t smem = smem_u32(dyn_smem);
    const int tid = threadIdx.x;
    const int lane = tid & 31;
    const int wid = tid >> 5;
    const int wm = wid >> 2, wn = wid & 3;
    const int b = blockIdx.z;
    const int tile_m = blockIdx.y * 128;   // t
    const int tile_n = blockIdx.x * 128;   // d

    float acc[4][4][4];
    gemm_main(g_Phi + ((size_t)b * TT + tile_m) * TT,
              g_Plo + ((size_t)b * TT + tile_m) * TT, TT,
              g_SThi + ((size_t)b * DD + tile_n) * TT,
              g_STlo + ((size_t)b * DD + tile_n) * TT, TT,
              TT / KC, smem, acc);

    const float* Vb = V + (size_t)b * TT * DD;
    float* Ob = Out + (size_t)b * TT * DD;
    const float* sums = g_sums + b * TT;
#pragma unroll
    for (int mt = 0; mt < 4; mt++) {
        const int r0 = tile_m + wm * 64 + mt * 16 + (lane >> 2);
        const int r1 = r0 + 8;
        const float inv0 = 1.0f / sums[r0];
        const float inv1 = 1.0f / sums[r1];
#pragma unroll
        for (int nt = 0; nt < 4; nt++) {
            const int c0 = tile_n + wn * 32 + nt * 8 + (lane & 3) * 2;
            float2 v0 = *reinterpret_cast<const float2*>(Vb + (size_t)r0 * DD + c0);
            float2 v1 = *reinterpret_cast<const float2*>(Vb + (size_t)r1 * DD + c0);
            float2 o0, o1;
            o0.x = acc[mt][nt][0] * inv0 * v0.x;
            o0.y = acc[mt][nt][1] * inv0 * v0.y;
            o1.x = acc[mt][nt][2] * inv1 * v1.x;
            o1.y = acc[mt][nt][3] * inv1 * v1.y;
            *reinterpret_cast<float2*>(Ob + (size_t)r0 * DD + c0) = o0;
            *reinterpret_cast<float2*>(Ob + (size_t)r1 * DD + c0) = o1;
        }
    }
}

// ---------------- fp32 -> bf16 hi/lo conversions ---------------------------
// Destinations resolved IN DEVICE CODE (host-side __device__ symbol args give
// the host shadow address -> silent ATS writes to host memory; R4/R5 bug).
__global__ __launch_bounds__(256) void conv_hl_kernel(const float* __restrict__ src,
                                                      int which) {
    bf16* hi = (which == 0) ? g_Qhi : g_Khi;
    bf16* lo = (which == 0) ? g_Qlo : g_Klo;
    size_t i4 = (size_t)blockIdx.x * 256 + threadIdx.x;
    float4 v = reinterpret_cast<const float4*>(src)[i4];
    bf16 h0 = __float2bfloat16(v.x), h1 = __float2bfloat16(v.y);
    bf16 h2 = __float2bfloat16(v.z), h3 = __float2bfloat16(v.w);
    bf16 l0 = __float2bfloat16(v.x - __bfloat162float(h0));
    bf16 l1 = __float2bfloat16(v.y - __bfloat162float(h1));
    bf16 l2 = __float2bfloat16(v.z - __bfloat162float(h2));
    bf16 l3 = __float2bfloat16(v.w - __bfloat162float(h3));
    reinterpret_cast<uint2*>(hi)[i4] = make_uint2(pk(h0, h1), pk(h2, h3));
    reinterpret_cast<uint2*>(lo)[i4] = make_uint2(pk(l0, l1), pk(l2, l3));
}

// transpose S[b][t][d] -> St[b][d][t] with hi/lo split
__global__ void conv_sT_kernel(const float* __restrict__ S) {
    __shared__ float t[32][33];
    const int b = blockIdx.z;
    const int t0 = blockIdx.x * 32, d0 = blockIdx.y * 32;
    const int x = threadIdx.x, y = threadIdx.y;
    const float* Sb = S + (size_t)b * TT * DD;
#pragma unroll
    for (int i = 0; i < 32; i += 8)
        t[y + i][x] = Sb[(size_t)(t0 + y + i) * DD + d0 + x];
    __syncthreads();
    bf16* Hb = g_SThi + (size_t)b * DD * TT;
    bf16* Lb = g_STlo + (size_t)b * DD * TT;
#pragma unroll
    for (int i = 0; i < 32; i += 8) {
        const int d = d0 + y + i;
        float v = t[x][y + i];
        bf16 h = __float2bfloat16(v);
        Hb[(size_t)d * TT + t0 + x] = h;
        Lb[(size_t)d * TT + t0 + x] = __float2bfloat16(v - __bfloat162float(h));
    }
}

// ---------------- host -----------------------------------------------------
extern "C" void kernel_launch(void* const* d_in, const int* in_sizes, int n_in,
                              void* d_out, int out_size) {
    const float* q = (const float*)d_in[0];
    const float* k = (const float*)d_in[1];
    const float* v = (const float*)d_in[2];
    const float* s = (const float*)d_in[3];
    float* out = (float*)d_out;

    cudaFuncSetAttribute(qk_kernel, cudaFuncAttributeMaxDynamicSharedMemorySize, DYN_SMEM);
    cudaFuncSetAttribute(pv_kernel, cudaFuncAttributeMaxDynamicSharedMemorySize, DYN_SMEM);

    const int n4 = BB * TT * DD / 4;
    conv_hl_kernel<<<n4 / 256, 256>>>(q, 0);
    conv_hl_kernel<<<n4 / 256, 256>>>(k, 1);
    conv_sT_kernel<<<dim3(TT / 32, DD / 32, BB), dim3(32, 8)>>>(s);

    qk_kernel<<<dim3(TT / 128, TT / 128, BB), 256, DYN_SMEM>>>();
    sumpart_kernel<<<BB * TT / 8, 256>>>();
    pv_kernel<<<dim3(DD / 128, TT / 128, BB), 256, DYN_SMEM>>>(v, out);
}

// round 11
// speedup vs baseline: 2.5976x; 1.0475x over previous
#include <cuda_runtime.h>
#include <cuda_bf16.h>
#include <cstdint>

#define BB 8
#define TT 2048
#define DD 512
#define KC 32                       // k-chunk (bf16 elements)
#define PITCH 40                    // smem row pitch in bf16 (32 data + 8 pad) = 80B
#define ARR (128 * PITCH * 2)       // one array: 10240 B
#define SB (4 * ARR)                // stage: Ah, Al, Bh, Bl = 40960 B
#define DYN_SMEM (2 * SB)           // 81920 B -> 2 CTAs/SM

typedef __nv_bfloat16 bf16;

// ---------------- global scratch ----------------
__device__ __align__(1024) bf16 g_Qhi[(size_t)BB * TT * DD];
__device__ __align__(1024) bf16 g_Qlo[(size_t)BB * TT * DD];
__device__ __align__(1024) bf16 g_Khi[(size_t)BB * TT * DD];
__device__ __align__(1024) bf16 g_Klo[(size_t)BB * TT * DD];
__device__ __align__(1024) bf16 g_SThi[(size_t)BB * DD * TT];  // [b][d][t]
__device__ __align__(1024) bf16 g_STlo[(size_t)BB * DD * TT];
__device__ __align__(1024) bf16 g_Phi[(size_t)BB * TT * TT];
__device__ __align__(1024) bf16 g_Plo[(size_t)BB * TT * TT];
__device__ float g_part[(size_t)BB * TT * 64];   // per-(row, tile_x*4+wn) partial sums
__device__ float g_sums[BB * TT];

// ---------------- PTX helpers (sm_80-era, legal on compute_103) ------------
__device__ __forceinline__ uint32_t smem_u32(const void* p) {
    uint32_t a;
    asm("{ .reg .u64 t; cvta.to.shared.u64 t, %1; cvt.u32.u64 %0, t; }" : "=r"(a) : "l"(p));
    return a;
}
__device__ __forceinline__ void cp16(uint32_t dst, const void* src) {
    asm volatile("cp.async.cg.shared.global [%0], [%1], 16;" :: "r"(dst), "l"(src) : "memory");
}
__device__ __forceinline__ void cp_commit() {
    asm volatile("cp.async.commit_group;" ::: "memory");
}
__device__ __forceinline__ void cp_wait1() {
    asm volatile("cp.async.wait_group 1;" ::: "memory");
}
__device__ __forceinline__ void cp_wait0() {
    asm volatile("cp.async.wait_group 0;" ::: "memory");
}
__device__ __forceinline__ void ldm_x4(uint32_t* d, uint32_t addr) {
    asm volatile("ldmatrix.sync.aligned.m8n8.x4.shared.b16 {%0,%1,%2,%3}, [%4];"
                 : "=r"(d[0]), "=r"(d[1]), "=r"(d[2]), "=r"(d[3]) : "r"(addr));
}
__device__ __forceinline__ void mma16816(float* c, const uint32_t* a, const uint32_t* b) {
    asm volatile(
        "mma.sync.aligned.m16n8k16.row.col.f32.bf16.bf16.f32 "
        "{%0,%1,%2,%3}, {%4,%5,%6,%7}, {%8,%9}, {%0,%1,%2,%3};"
        : "+f"(c[0]), "+f"(c[1]), "+f"(c[2]), "+f"(c[3])
        : "r"(a[0]), "r"(a[1]), "r"(a[2]), "r"(a[3]), "r"(b[0]), "r"(b[1]));
}
__device__ __forceinline__ float ex2(float x) {
    float r;
    asm("ex2.approx.ftz.f32 %0, %1;" : "=f"(r) : "f"(x));
    return r;
}
__device__ __forceinline__ unsigned pk(bf16 a, bf16 b) {
    __nv_bfloat162 t = __halves2bfloat162(a, b);
    return *reinterpret_cast<unsigned*>(&t);
}

// ---------------- stage loader: rows 0..127, 4x16B chunks per row ----------
__device__ __forceinline__ void ldstage(uint32_t st,
                                        const bf16* ah, const bf16* al, size_t lda,
                                        const bf16* bh, const bf16* bl, size_t ldb,
                                        int k0, int tid) {
#pragma unroll
    for (int it = 0; it < 2; it++) {
        int f = tid + it * 256;            // 0..511
        int r = f >> 2, c = f & 3;
        uint32_t d = st + (uint32_t)(r * (PITCH * 2) + c * 16);
        size_t oa = (size_t)r * lda + k0 + c * 8;
        size_t ob = (size_t)r * ldb + k0 + c * 8;
        cp16(d,            ah + oa);
        cp16(d + ARR,      al + oa);
        cp16(d + 2 * ARR,  bh + ob);
        cp16(d + 3 * ARR,  bl + ob);
    }
}

// ---------------- HMMA mainloop: D(128x128) = A @ B^T, 3-term split --------
// R10-validated math; restructured loads: B fragments hoisted per k16 step via
// paired ldmatrix.x4 (one instr = both k-halves of two nt blocks), A streamed
// per mt. Cuts LDSM/warp/ks 16->12 and live fragment regs 40->~24.
__device__ __forceinline__ void gemm_main(const bf16* ah, const bf16* al, size_t lda,
                                          const bf16* bh, const bf16* bl, size_t ldb,
                                          int NC, uint32_t smem, float acc[4][4][4]) {
    const int tid = threadIdx.x;
    const int lane = tid & 31;
    const int wid = tid >> 5;
    const int wm = wid >> 2;      // 0..1 -> 64-row half
    const int wn = wid & 3;       // 0..3 -> 32-col quarter

#pragma unroll
    for (int mt = 0; mt < 4; mt++)
#pragma unroll
        for (int nt = 0; nt < 4; nt++)
#pragma unroll
            for (int u = 0; u < 4; u++) acc[mt][nt][u] = 0.f;

    // A ldmatrix.x4 lane roles: matrices = (row-half0,k0),(row-half1,k0)... per PTX:
    // groups 0-7 / 8-15 / 16-23 / 24-31 address matrices 0..3.
    const int arow = lane & 15;          // A row within 16-row block (groups 0,1: rows; 2,3: +k-half)
    const int akc  = lane >> 4;          // 0/1: k half (16B)
    // B paired-x4 lane roles: matrix m = (nt offset m>>1, k-half m&1)
    const int brow = lane & 7;
    const int bkc  = (lane >> 3) & 1;    // k half select
    const int bnt  = (lane >> 4) & 1;    // nt-within-pair select

    ldstage(smem, ah, al, lda, bh, bl, ldb, 0, tid);
    cp_commit();

    for (int i = 0; i < NC; i++) {
        const int j = i + 1;
        if (j < NC) {
            ldstage(smem + (j & 1) * SB, ah, al, lda, bh, bl, ldb, j * KC, tid);
            cp_commit();
            cp_wait1();
        } else {
            cp_wait0();
        }
        __syncthreads();

        const uint32_t sa = smem + (i & 1) * SB;
#pragma unroll
        for (int ks = 0; ks < 2; ks++) {
            // hoist B fragments for all 4 nt (hi & lo): 4 x4-ldmatrix
            uint32_t bfh[4][2], bfl[4][2];
#pragma unroll
            for (int np = 0; np < 2; np++) {
                uint32_t baddr = sa + 2 * ARR
                    + (uint32_t)((wn * 32 + (np * 2 + bnt) * 8 + brow) * (PITCH * 2))
                    + (uint32_t)((ks * 2 + bkc) * 16);
                uint32_t t[4];
                ldm_x4(t, baddr);
                bfh[np * 2][0] = t[0]; bfh[np * 2][1] = t[1];
                bfh[np * 2 + 1][0] = t[2]; bfh[np * 2 + 1][1] = t[3];
                ldm_x4(t, baddr + ARR);
                bfl[np * 2][0] = t[0]; bfl[np * 2][1] = t[1];
                bfl[np * 2 + 1][0] = t[2]; bfl[np * 2 + 1][1] = t[3];
            }
            // stream A per mt: 2 x4-ldmatrix -> 12 MMAs
#pragma unroll
            for (int mt = 0; mt < 4; mt++) {
                uint32_t aaddr = sa
                    + (uint32_t)((wm * 64 + mt * 16 + arow) * (PITCH * 2))
                    + (uint32_t)((ks * 2 + akc) * 16);
                uint32_t afh[4], afl[4];
                ldm_x4(afh, aaddr);
                ldm_x4(afl, aaddr + ARR);
#pragma unroll
                for (int nt = 0; nt < 4; nt++) {
                    mma16816(acc[mt][nt], afh, bfh[nt]);
                    mma16816(acc[mt][nt], afh, bfl[nt]);
                    mma16816(acc[mt][nt], afl, bfh[nt]);
                }
            }
        }
        __syncthreads();
    }
}

// ---------------- K1: P~ = exp(QK^T * scale) -> bf16 hi/lo + partial sums --
__global__ __launch_bounds__(256, 2) void qk_kernel() {
    extern __shared__ char dyn_smem[];
    const uint32_t smem = smem_u32(dyn_smem);
    const int tid = threadIdx.x;
    const int lane = tid & 31;
    const int wid = tid >> 5;
    const int wm = wid >> 2, wn = wid & 3;
    const int q = lane & 3;
    const int b = blockIdx.z;
    const int tile_m = blockIdx.y * 128;
    const int tile_n = blockIdx.x * 128;

    float acc[4][4][4];
    gemm_main(g_Qhi + ((size_t)b * TT + tile_m) * DD,
              g_Qlo + ((size_t)b * TT + tile_m) * DD, DD,
              g_Khi + ((size_t)b * TT + tile_n) * DD,
              g_Klo + ((size_t)b * TT + tile_n) * DD, DD,
              DD / KC, smem, acc);

    const float SCL = 1.4426950408889634f * 0.04419417382415922f;
    bf16* Ph = g_Phi + (size_t)b * TT * TT;
    bf16* Pl = g_Plo + (size_t)b * TT * TT;
#pragma unroll
    for (int mt = 0; mt < 4; mt++) {
        const int r0 = tile_m + wm * 64 + mt * 16 + (lane >> 2);
        const int r1 = r0 + 8;
        float rs0 = 0.f, rs1 = 0.f;
#pragma unroll
        for (int nt = 0; nt < 4; nt++) {
            const int c0 = tile_n + wn * 32 + nt * 8 + q * 2;
            float p0 = ex2(acc[mt][nt][0] * SCL);
            float p1 = ex2(acc[mt][nt][1] * SCL);
            float p2 = ex2(acc[mt][nt][2] * SCL);
            float p3 = ex2(acc[mt][nt][3] * SCL);
            rs0 += p0 + p1;
            rs1 += p2 + p3;
            bf16 h0 = __float2bfloat16(p0), h1 = __float2bfloat16(p1);
            bf16 h2 = __float2bfloat16(p2), h3 = __float2bfloat16(p3);
            bf16 l0 = __float2bfloat16(p0 - __bfloat162float(h0));
            bf16 l1 = __float2bfloat16(p1 - __bfloat162float(h1));
            bf16 l2 = __float2bfloat16(p2 - __bfloat162float(h2));
            bf16 l3 = __float2bfloat16(p3 - __bfloat162float(h3));
            *reinterpret_cast<uint32_t*>(Ph + (size_t)r0 * TT + c0) = pk(h0, h1);
            *reinterpret_cast<uint32_t*>(Ph + (size_t)r1 * TT + c0) = pk(h2, h3);
            *reinterpret_cast<uint32_t*>(Pl + (size_t)r0 * TT + c0) = pk(l0, l1);
            *reinterpret_cast<uint32_t*>(Pl + (size_t)r1 * TT + c0) = pk(l2, l3);
        }
        // reduce across the quad (lanes sharing a row) -> per-warp row partials
        rs0 += __shfl_xor_sync(0xFFFFFFFFu, rs0, 1);
        rs0 += __shfl_xor_sync(0xFFFFFFFFu, rs0, 2);
        rs1 += __shfl_xor_sync(0xFFFFFFFFu, rs1, 1);
        rs1 += __shfl_xor_sync(0xFFFFFFFFu, rs1, 2);
        if (q == 0) {
            const int col = blockIdx.x * 4 + wn;
            g_part[((size_t)b * TT + r0) * 64 + col] = rs0;
            g_part[((size_t)b * TT + r1) * 64 + col] = rs1;
        }
    }
}

// ---------------- reduce 64 partials per row -> g_sums ---------------------
__global__ __launch_bounds__(256) void sumpart_kernel() {
    const int row = blockIdx.x * 8 + (threadIdx.x >> 5);
    const int lane = threadIdx.x & 31;
    const float* p = g_part + (size_t)row * 64;
    float s = p[lane] + p[lane + 32];
#pragma unroll
    for (int o = 16; o; o >>= 1) s += __shfl_xor_sync(0xFFFFFFFFu, s, o);
    if (lane == 0) g_sums[row] = s;
}

// ---------------- K3: out = (P~ @ S) * V / rowsum --------------------------
__global__ __launch_bounds__(256, 2) void pv_kernel(const float* __restrict__ V,
                                                    float* __restrict__ Out) {
    extern __shared__ char dyn_smem[];
    const uint32_t smem = smem_u32(dyn_smem);
    const int tid = threadIdx.x;
    const int lane = tid & 31;
    const int wid = tid >> 5;
    const int wm = wid >> 2, wn = wid & 3;
    const int b = blockIdx.z;
    const int tile_m = blockIdx.y * 128;   // t
    const int tile_n = blockIdx.x * 128;   // d

    float acc[4][4][4];
    gemm_main(g_Phi + ((size_t)b * TT + tile_m) * TT,
              g_Plo + ((size_t)b * TT + tile_m) * TT, TT,
              g_SThi + ((size_t)b * DD + tile_n) * TT,
              g_STlo + ((size_t)b * DD + tile_n) * TT, TT,
              TT / KC, smem, acc);

    const float* Vb = V + (size_t)b * TT * DD;
    float* Ob = Out + (size_t)b * TT * DD;
    const float* sums = g_sums + b * TT;
#pragma unroll
    for (int mt = 0; mt < 4; mt++) {
        const int r0 = tile_m + wm * 64 + mt * 16 + (lane >> 2);
        const int r1 = r0 + 8;
        const float inv0 = 1.0f / sums[r0];
        const float inv1 = 1.0f / sums[r1];
#pragma unroll
        for (int nt = 0; nt < 4; nt++) {
            const int c0 = tile_n + wn * 32 + nt * 8 + (lane & 3) * 2;
            float2 v0 = *reinterpret_cast<const float2*>(Vb + (size_t)r0 * DD + c0);
            float2 v1 = *reinterpret_cast<const float2*>(Vb + (size_t)r1 * DD + c0);
            float2 o0, o1;
            o0.x = acc[mt][nt][0] * inv0 * v0.x;
            o0.y = acc[mt][nt][1] * inv0 * v0.y;
            o1.x = acc[mt][nt][2] * inv1 * v1.x;
            o1.y = acc[mt][nt][3] * inv1 * v1.y;
            *reinterpret_cast<float2*>(Ob + (size_t)r0 * DD + c0) = o0;
            *reinterpret_cast<float2*>(Ob + (size_t)r1 * DD + c0) = o1;
        }
    }
}

// ---------------- fp32 -> bf16 hi/lo conversions ---------------------------
// Destinations resolved IN DEVICE CODE (host-side __device__ symbol args give
// the host shadow address -> silent ATS writes to host memory; R4/R5 bug).
__global__ __launch_bounds__(256) void conv_hl_kernel(const float* __restrict__ src,
                                                      int which) {
    bf16* hi = (which == 0) ? g_Qhi : g_Khi;
    bf16* lo = (which == 0) ? g_Qlo : g_Klo;
    size_t i4 = (size_t)blockIdx.x * 256 + threadIdx.x;
    float4 v = reinterpret_cast<const float4*>(src)[i4];
    bf16 h0 = __float2bfloat16(v.x), h1 = __float2bfloat16(v.y);
    bf16 h2 = __float2bfloat16(v.z), h3 = __float2bfloat16(v.w);
    bf16 l0 = __float2bfloat16(v.x - __bfloat162float(h0));
    bf16 l1 = __float2bfloat16(v.y - __bfloat162float(h1));
    bf16 l2 = __float2bfloat16(v.z - __bfloat162float(h2));
    bf16 l3 = __float2bfloat16(v.w - __bfloat162float(h3));
    reinterpret_cast<uint2*>(hi)[i4] = make_uint2(pk(h0, h1), pk(h2, h3));
    reinterpret_cast<uint2*>(lo)[i4] = make_uint2(pk(l0, l1), pk(l2, l3));
}

// transpose S[b][t][d] -> St[b][d][t] with hi/lo split
__global__ void conv_sT_kernel(const float* __restrict__ S) {
    __shared__ float t[32][33];
    const int b = blockIdx.z;
    const int t0 = blockIdx.x * 32, d0 = blockIdx.y * 32;
    const int x = threadIdx.x, y = threadIdx.y;
    const float* Sb = S + (size_t)b * TT * DD;
#pragma unroll
    for (int i = 0; i < 32; i += 8)
        t[y + i][x] = Sb[(size_t)(t0 + y + i) * DD + d0 + x];
    __syncthreads();
    bf16* Hb = g_SThi + (size_t)b * DD * TT;
    bf16* Lb = g_STlo + (size_t)b * DD * TT;
#pragma unroll
    for (int i = 0; i < 32; i += 8) {
        const int d = d0 + y + i;
        float v = t[x][y + i];
        bf16 h = __float2bfloat16(v);
        Hb[(size_t)d * TT + t0 + x] = h;
        Lb[(size_t)d * TT + t0 + x] = __float2bfloat16(v - __bfloat162float(h));
    }
}

// ---------------- host -----------------------------------------------------
extern "C" void kernel_launch(void* const* d_in, const int* in_sizes, int n_in,
                              void* d_out, int out_size) {
    const float* q = (const float*)d_in[0];
    const float* k = (const float*)d_in[1];
    const float* v = (const float*)d_in[2];
    const float* s = (const float*)d_in[3];
    float* out = (float*)d_out;

    cudaFuncSetAttribute(qk_kernel, cudaFuncAttributeMaxDynamicSharedMemorySize, DYN_SMEM);
    cudaFuncSetAttribute(pv_kernel, cudaFuncAttributeMaxDynamicSharedMemorySize, DYN_SMEM);

    const int n4 = BB * TT * DD / 4;
    conv_hl_kernel<<<n4 / 256, 256>>>(q, 0);
    conv_hl_kernel<<<n4 / 256, 256>>>(k, 1);
    conv_sT_kernel<<<dim3(TT / 32, DD / 32, BB), dim3(32, 8)>>>(s);

    qk_kernel<<<dim3(TT / 128, TT / 128, BB), 256, DYN_SMEM>>>();
    sumpart_kernel<<<BB * TT / 8, 256>>>();
    pv_kernel<<<dim3(DD / 128, TT / 128, BB), 256, DYN_SMEM>>>(v, out);
}